// round 6
// baseline (speedup 1.0000x reference)
#include <cuda_runtime.h>
#include <cstdint>

#define SEQ_LEN  120
#define BATCH    2048
#define INPUT    6
#define HID      64
#define GATES    256
#define LAYERS   4
#define TLEN     120
#define NB       16
#define NCTA     (BATCH / NB)   // 128
#define NTHR     256

#define CHUNK_ROWS 32
#define CHUNK_F4   (CHUNK_ROWS * HID)     // 2048 float4
#define CHUNK_BYTES (CHUNK_F4 * 16)       // 32768
#define NSLOT      5
#define CPS        15
#define TOTALC     (240 * CPS)

typedef unsigned long long ull;

// flat periodic streams, chunk order per layer: Whh halves first, then Wih.
// chunks: c0,c1=Whh0 ; c2=W0(k-padded) ; per l>=1 base 3+4(l-1): Whh l (2), Wih l (2)
__device__ float4 g_stream_e[CPS * CHUNK_F4];
__device__ float4 g_stream_d[CPS * CHUNK_F4];

__global__ void lstm36206574305735_pack(
    const float* __restrict__ eW0, const float* __restrict__ eWih,
    const float* __restrict__ eWhh, const float* __restrict__ dW0,
    const float* __restrict__ dWih, const float* __restrict__ dWhh)
{
    const int tot = 2 * CPS * CHUNK_F4;
    for (int idx = blockIdx.x * blockDim.x + threadIdx.x; idx < tot;
         idx += gridDim.x * blockDim.x) {
        int p  = idx / (CPS * CHUNK_F4);
        int r  = idx % (CPS * CHUNK_F4);
        int c  = r / CHUNK_F4;
        int rr = r % CHUNK_F4;
        int kc = rr / HID;
        int hh = rr % HID;
        const float* W0  = p ? dW0  : eW0;
        const float* Wih = p ? dWih : eWih;
        const float* Whh = p ? dWhh : eWhh;
        float4 v = make_float4(0.f, 0.f, 0.f, 0.f);
        if (c == 2) {
            if (kc < INPUT) {
                v.x = W0[(0 * HID + hh) * INPUT + kc];
                v.y = W0[(1 * HID + hh) * INPUT + kc];
                v.z = W0[(2 * HID + hh) * INPUT + kc];
                v.w = W0[(3 * HID + hh) * INPUT + kc];
            }
        } else {
            const float* W; int k;
            if (c < 2) { W = Whh; k = c * CHUNK_ROWS + kc; }           // Whh L0
            else {
                int l  = (c - 3) / 4 + 1;
                int cc = (c - 3) % 4;
                if (cc < 2) { W = Whh + (size_t)l * GATES * HID;       k = cc * CHUNK_ROWS + kc; }
                else        { W = Wih + (size_t)(l - 1) * GATES * HID; k = (cc - 2) * CHUNK_ROWS + kc; }
            }
            v.x = W[(0 * HID + hh) * HID + k];
            v.y = W[(1 * HID + hh) * HID + k];
            v.z = W[(2 * HID + hh) * HID + k];
            v.w = W[(3 * HID + hh) * HID + k];
        }
        (p ? g_stream_d : g_stream_e)[r] = v;
    }
}

// ---- helpers ----------------------------------------------------------------
__device__ __forceinline__ void ffma2(ull& d, ull a, ull b) {
    asm("fma.rn.f32x2 %0, %1, %2, %0;" : "+l"(d) : "l"(a), "l"(b));
}
__device__ __forceinline__ ull pk(float a, float b) {
    ull v; asm("mov.b64 %0, {%1, %2};" : "=l"(v) : "f"(a), "f"(b)); return v;
}
__device__ __forceinline__ float2 unpk(ull v) {
    float2 r; asm("mov.b64 {%0, %1}, %2;" : "=f"(r.x), "=f"(r.y) : "l"(v)); return r;
}
__device__ __forceinline__ float fsig(float x) {
    return __fdividef(1.0f, 1.0f + __expf(-x));
}
__device__ __forceinline__ float ftanh_(float x) {
    return 2.0f * fsig(2.0f * x) - 1.0f;
}
__device__ __forceinline__ uint32_t smem_u32(const void* p) {
    uint32_t a;
    asm("{ .reg .u64 t; cvta.to.shared.u64 t, %1; cvt.u32.u64 %0, t; }"
        : "=r"(a) : "l"(p));
    return a;
}
__device__ __forceinline__ void wait_parity(uint32_t mb, uint32_t parity) {
    asm volatile(
        "{\n\t"
        ".reg .pred P;\n\t"
        "WLOOP_%=:\n\t"
        "mbarrier.try_wait.parity.acquire.cta.shared::cta.b64 P, [%0], %1, 0x989680;\n\t"
        "@P bra WDONE_%=;\n\t"
        "bra WLOOP_%=;\n\t"
        "WDONE_%=:\n\t"
        "}"
        :: "r"(mb), "r"(parity) : "memory");
}

// gemv: per k = 3 LDS.128 + 8 FFMA2, zero MOVs.
// wslot: ulonglong2 {(wi,wf),(wg,wo)} per (k,hh); hs: dup'd h [k][32]
template <int K>
__device__ __forceinline__ void gemv_p(const ulonglong2* __restrict__ wslot,
                                       const float* __restrict__ hs,
                                       int hh, int bg, ull aif[4], ull ago[4])
{
#pragma unroll 4
    for (int k = 0; k < K; k++) {
        ulonglong2 wv = wslot[k * HID + hh];
        ulonglong2 ha = *(const ulonglong2*)(hs + k * 32 + bg * 8);
        ulonglong2 hb = *(const ulonglong2*)(hs + k * 32 + bg * 8 + 4);
        ffma2(aif[0], wv.x, ha.x); ffma2(ago[0], wv.y, ha.x);
        ffma2(aif[1], wv.x, ha.y); ffma2(ago[1], wv.y, ha.y);
        ffma2(aif[2], wv.x, hb.x); ffma2(ago[2], wv.y, hb.x);
        ffma2(aif[3], wv.x, hb.y); ffma2(ago[3], wv.y, hb.y);
    }
}

// ---- smem layout ------------------------------------------------------------
#define RING_SZ   (NSLOT * CHUNK_BYTES)     // 163840
#define MBAR_B    RING_SZ
#define FB_B      (RING_SZ + 64)
#define HD_F      0                          // [4][64][32] dup'd h (single buffer)
#define SZ_HD     (LAYERS * HID * 32)        // 8192
#define IND_F     (HD_F + SZ_HD)             // [8][32] dup'd, rows 6,7 zero
#define SZ_IND    (8 * 32)
#define LW_F      (IND_F + SZ_IND)
#define LB_F      (LW_F + HID * INPUT)
#define BIAS_F    (LB_F + 8)                 // [2][4][64] ulonglong2 = 2048 floats
#define SZ_BIAS   (2 * LAYERS * HID * 4)
#define SMEM_TOTAL_B (FB_B + (BIAS_F + SZ_BIAS) * 4)

__global__ void __launch_bounds__(NTHR, 1)
lstm36206574305735_main(const float* __restrict__ x,
                        const float* __restrict__ eB,
                        const float* __restrict__ dB,
                        const float* __restrict__ linW,
                        const float* __restrict__ linB,
                        float* __restrict__ out)
{
    extern __shared__ char sm[];
    const uint32_t ring_u = smem_u32(sm);
    const uint32_t mbar_u = ring_u + MBAR_B;
    float* fb   = (float*)(sm + FB_B);
    float* hd   = fb + HD_F;
    float* ind  = fb + IND_F;
    float* lw_s = fb + LW_F;
    float* lb_s = fb + LB_F;
    ulonglong2* bias = (ulonglong2*)(fb + BIAS_F);

    const int tid = threadIdx.x;
    const int hh  = tid >> 2;
    const int bg  = tid & 3;
    const int b0  = blockIdx.x * NB;

    if (tid == 0) {
        for (int s = 0; s < NSLOT; s++)
            asm volatile("mbarrier.init.shared.b64 [%0], 1;"
                         :: "r"(mbar_u + s * 8) : "memory");
        asm volatile("fence.proxy.async.shared::cta;" ::: "memory");
    }
    for (int i = tid; i < SZ_HD; i += NTHR) hd[i] = 0.0f;
    for (int i = tid; i < SZ_IND; i += NTHR) ind[i] = 0.0f;
    for (int i = tid; i < HID * INPUT; i += NTHR) {
        int h2 = i / INPUT, ii2 = i % INPUT;
        lw_s[h2 * INPUT + ii2] = linW[ii2 * HID + h2];
    }
    if (tid < INPUT) lb_s[tid] = linB[tid];
    for (int u = tid; u < 2 * LAYERS * HID; u += NTHR) {
        int phase = u >> 8, l = (u >> 6) & 3, hx = u & 63;
        const float* B = phase ? dB : eB;
        ulonglong2 v;
        v.x = pk(B[l * GATES + hx],           B[l * GATES + HID + hx]);
        v.y = pk(B[l * GATES + 2 * HID + hx], B[l * GATES + 3 * HID + hx]);
        bias[u] = v;
    }
    __syncthreads();

    // initial prefetch
    auto issue_one = [&](int G) {
        if (G >= TOTALC) return;
        int s = G % NSLOT;
        const float4* src = (G < 120 * CPS ? g_stream_e : g_stream_d)
                            + (size_t)(G % CPS) * CHUNK_F4;
        uint32_t mb = mbar_u + s * 8;
        asm volatile("mbarrier.arrive.expect_tx.shared.b64 _, [%0], %1;"
                     :: "r"(mb), "r"((uint32_t)CHUNK_BYTES) : "memory");
        asm volatile("cp.async.bulk.shared::cluster.global.mbarrier::complete_tx::bytes "
                     "[%0], [%1], %2, [%3];"
                     :: "r"(ring_u + (uint32_t)s * CHUNK_BYTES), "l"(src),
                        "r"((uint32_t)CHUNK_BYTES), "r"(mb) : "memory");
    };
    if (tid == 0)
        for (int g = 0; g < NSLOT; g++) issue_one(g);

    int Gi = NSLOT, cap = NSLOT, Cg = 0;
    unsigned par = 0;

    auto next_chunk = [&]() -> const ulonglong2* {
        int s = Cg % NSLOT;
        wait_parity(mbar_u + s * 8, (par >> s) & 1u);
        par ^= (1u << s);
        Cg++;
        return (const ulonglong2*)(sm + (size_t)s * CHUNK_BYTES);
    };
    auto barrier_issue = [&](int add) {
        __syncthreads();
        cap += add;
        if (tid == 0)
            for (; Gi < cap; Gi++) issue_one(Gi);
        else
            Gi = cap;
    };

    float c_reg[LAYERS][4];
#pragma unroll
    for (int l = 0; l < LAYERS; l++)
#pragma unroll
        for (int bi = 0; bi < 4; bi++) c_reg[l][bi] = 0.0f;

    const int  bb  = tid / INPUT;
    const int  ii  = tid % INPUT;
    const bool isx = tid < INPUT * NB;
    float xreg = 0.0f;
    if (isx) xreg = x[(size_t)(b0 + bb) * INPUT + ii];

    // one layer: Whh gemv -> barrier(+issue) -> Wih/W0 gemv -> cell epilogue
    auto do_layer = [&](int phase, int l, int add, bool isL0) {
        ulonglong2 bv = bias[(phase * LAYERS + l) * HID + hh];
        ull aif[4], ago[4];
#pragma unroll
        for (int bi = 0; bi < 4; bi++) { aif[bi] = bv.x; ago[bi] = bv.y; }

        const float* hl = hd + l * (HID * 32);
        { const ulonglong2* wp = next_chunk(); gemv_p<32>(wp, hl,        hh, bg, aif, ago); }
        { const ulonglong2* wp = next_chunk(); gemv_p<32>(wp, hl + 1024, hh, bg, aif, ago); }

        barrier_issue(add);

        if (isL0) {
            const ulonglong2* wp = next_chunk(); gemv_p<8>(wp, ind, hh, bg, aif, ago);
        } else {
            const float* hp = hd + (l - 1) * (HID * 32);
            { const ulonglong2* wp = next_chunk(); gemv_p<32>(wp, hp,        hh, bg, aif, ago); }
            { const ulonglong2* wp = next_chunk(); gemv_p<32>(wp, hp + 1024, hh, bg, aif, ago); }
        }

        float hout[4];
#pragma unroll
        for (int bi = 0; bi < 4; bi++) {
            float2 sif = unpk(aif[bi]);
            float2 sgo = unpk(ago[bi]);
            float c = fmaf(fsig(sif.y), c_reg[l][bi], fsig(sif.x) * ftanh_(sgo.x));
            c_reg[l][bi] = c;
            hout[bi] = fsig(sgo.y) * ftanh_(c);
        }
        float* hrow = hd + (l * HID + hh) * 32 + bg * 8;
        *(float4*)hrow       = make_float4(hout[0], hout[0], hout[1], hout[1]);
        *(float4*)(hrow + 4) = make_float4(hout[2], hout[2], hout[3], hout[3]);
    };

    // -------- encoder --------
    for (int t = 0; t < SEQ_LEN; t++) {
        if (isx) {
            ind[ii * 32 + 2 * bb]     = xreg;
            ind[ii * 32 + 2 * bb + 1] = xreg;
            if (t + 1 < SEQ_LEN)
                xreg = x[((size_t)(t + 1) * BATCH + b0 + bb) * INPUT + ii];
        }
        do_layer(0, 0, t == 0 ? 2 : 4, true);
        do_layer(0, 1, 3, false);
        do_layer(0, 2, 4, false);
        do_layer(0, 3, 4, false);
    }

    // -------- decoder --------
    for (int t = 0; t < TLEN; t++) {
        do_layer(1, 0, 4, true);
        do_layer(1, 1, 3, false);
        do_layer(1, 2, 4, false);
        do_layer(1, 3, 4, false);

        __syncthreads();   // h[3] complete before projection
        if (isx) {
            const float* htop = hd + 3 * (HID * 32);
            float v = lb_s[ii];
#pragma unroll 8
            for (int h2 = 0; h2 < HID; h2++)
                v += lw_s[h2 * INPUT + ii] * htop[h2 * 32 + 2 * bb];
            out[((size_t)t * BATCH + b0 + bb) * INPUT + ii] = v;
            ind[ii * 32 + 2 * bb]     = v;
            ind[ii * 32 + 2 * bb + 1] = v;
        }
    }
}

extern "C" void kernel_launch(void* const* d_in, const int* in_sizes, int n_in,
                              void* d_out, int out_size)
{
    const float* x    = (const float*)d_in[0];
    const float* eW0  = (const float*)d_in[1];
    const float* eWih = (const float*)d_in[2];
    const float* eWhh = (const float*)d_in[3];
    const float* eB   = (const float*)d_in[4];
    const float* dW0  = (const float*)d_in[5];
    const float* dWih = (const float*)d_in[6];
    const float* dWhh = (const float*)d_in[7];
    const float* dB   = (const float*)d_in[8];
    const float* linW = (const float*)d_in[9];
    const float* linB = (const float*)d_in[10];
    float* out = (float*)d_out;

    lstm36206574305735_pack<<<240, 256>>>(eW0, eWih, eWhh, dW0, dWih, dWhh);

    cudaFuncSetAttribute(lstm36206574305735_main,
                         cudaFuncAttributeMaxDynamicSharedMemorySize, SMEM_TOTAL_B);
    lstm36206574305735_main<<<NCTA, NTHR, SMEM_TOTAL_B>>>(x, eB, dB, linW, linB, out);
}

// round 7
// speedup vs baseline: 1.4877x; 1.4877x over previous
#include <cuda_runtime.h>
#include <cstdint>

#define SEQ_LEN  120
#define BATCH    2048
#define INPUT    6
#define HID      64
#define GATES    256
#define LAYERS   4
#define TLEN     120
#define NB       16
#define NCTA     (BATCH / NB)   // 128
#define NTHR     256

#define CHUNK_ROWS 32
#define CHUNK_F4   (CHUNK_ROWS * HID)     // 2048 float4
#define CHUNK_BYTES (CHUNK_F4 * 16)       // 32768
#define W0_BYTES   (8 * HID * 16)         // 8192 (only 8 k-rows used)
#define NSLOT      5
#define CPS        15
#define TOTALC     (240 * CPS)

typedef unsigned long long ull;

// chunk order per step: c0,c1 = Whh L0 halves; c2 = W0 (k-padded to 8 rows used);
// per l>=1, base 3+4(l-1): Whh l (2 chunks), then Wih l (2 chunks)
__device__ float4 g_stream_e[CPS * CHUNK_F4];
__device__ float4 g_stream_d[CPS * CHUNK_F4];

__global__ void lstm36206574305735_pack(
    const float* __restrict__ eW0, const float* __restrict__ eWih,
    const float* __restrict__ eWhh, const float* __restrict__ dW0,
    const float* __restrict__ dWih, const float* __restrict__ dWhh)
{
    const int tot = 2 * CPS * CHUNK_F4;
    for (int idx = blockIdx.x * blockDim.x + threadIdx.x; idx < tot;
         idx += gridDim.x * blockDim.x) {
        int p  = idx / (CPS * CHUNK_F4);
        int r  = idx % (CPS * CHUNK_F4);
        int c  = r / CHUNK_F4;
        int rr = r % CHUNK_F4;
        int kc = rr / HID;
        int hh = rr % HID;
        const float* W0  = p ? dW0  : eW0;
        const float* Wih = p ? dWih : eWih;
        const float* Whh = p ? dWhh : eWhh;
        float4 v = make_float4(0.f, 0.f, 0.f, 0.f);
        if (c == 2) {
            if (kc < INPUT) {
                v.x = W0[(0 * HID + hh) * INPUT + kc];
                v.y = W0[(1 * HID + hh) * INPUT + kc];
                v.z = W0[(2 * HID + hh) * INPUT + kc];
                v.w = W0[(3 * HID + hh) * INPUT + kc];
            }
        } else {
            const float* W; int k;
            if (c < 2) { W = Whh; k = c * CHUNK_ROWS + kc; }            // Whh L0
            else {
                int l  = (c - 3) / 4 + 1;
                int cc = (c - 3) % 4;
                if (cc < 2) { W = Whh + (size_t)l * GATES * HID;        k = cc * CHUNK_ROWS + kc; }
                else        { W = Wih + (size_t)(l - 1) * GATES * HID;  k = (cc - 2) * CHUNK_ROWS + kc; }
            }
            v.x = W[(0 * HID + hh) * HID + k];
            v.y = W[(1 * HID + hh) * HID + k];
            v.z = W[(2 * HID + hh) * HID + k];
            v.w = W[(3 * HID + hh) * HID + k];
        }
        (p ? g_stream_d : g_stream_e)[r] = v;
    }
}

// ---- helpers ----------------------------------------------------------------
__device__ __forceinline__ void ffma2(ull& d, ull a, ull b) {
    asm("fma.rn.f32x2 %0, %1, %2, %0;" : "+l"(d) : "l"(a), "l"(b));
}
__device__ __forceinline__ ull dup2(float a) {
    ull v; asm("mov.b64 %0, {%1, %1};" : "=l"(v) : "f"(a)); return v;
}
__device__ __forceinline__ float2 unpk(ull v) {
    float2 r; asm("mov.b64 {%0, %1}, %2;" : "=f"(r.x), "=f"(r.y) : "l"(v)); return r;
}
__device__ __forceinline__ float fsig(float x) {
    return __fdividef(1.0f, 1.0f + __expf(-x));
}
__device__ __forceinline__ float ftanh_(float x) {
    return 2.0f * fsig(2.0f * x) - 1.0f;
}
__device__ __forceinline__ uint32_t smem_u32(const void* p) {
    uint32_t a;
    asm("{ .reg .u64 t; cvta.to.shared.u64 t, %1; cvt.u32.u64 %0, t; }"
        : "=r"(a) : "l"(p));
    return a;
}
__device__ __forceinline__ void wait_parity(uint32_t mb, uint32_t parity) {
    asm volatile(
        "{\n\t"
        ".reg .pred P;\n\t"
        "WLOOP_%=:\n\t"
        "mbarrier.try_wait.parity.acquire.cta.shared::cta.b64 P, [%0], %1, 0x989680;\n\t"
        "@P bra WDONE_%=;\n\t"
        "bra WLOOP_%=;\n\t"
        "WDONE_%=:\n\t"
        "}"
        :: "r"(mb), "r"(parity) : "memory");
}

// R5 gemv: per k = 2 LDS.128 + 4 dup MOVs + 8 FFMA2; h NOT duplicated.
template <int K>
__device__ __forceinline__ void gemv_s(const float4* __restrict__ wslot,
                                       const float* __restrict__ hs,
                                       int hh, int bg, ull acc[8])
{
#pragma unroll 8
    for (int k = 0; k < K; k++) {
        float4 w4 = wslot[k * HID + hh];
        ulonglong2 hv = *(const ulonglong2*)(hs + k * 16 + bg * 4);
        ull wi = dup2(w4.x), wf = dup2(w4.y), wg = dup2(w4.z), wo = dup2(w4.w);
        ffma2(acc[0], wi, hv.x); ffma2(acc[1], wi, hv.y);
        ffma2(acc[2], wf, hv.x); ffma2(acc[3], wf, hv.y);
        ffma2(acc[4], wg, hv.x); ffma2(acc[5], wg, hv.y);
        ffma2(acc[6], wo, hv.x); ffma2(acc[7], wo, hv.y);
    }
}

// ---- smem layout ------------------------------------------------------------
#define RING_SZ   (NSLOT * CHUNK_BYTES)     // 163840
#define MBAR_B    RING_SZ
#define FB_B      (RING_SZ + 64)
#define HD_F      0                          // [4][64][16] single-buffered h
#define SZ_HD     (LAYERS * HID * 16)        // 4096
#define IND_F     (HD_F + SZ_HD)             // [8][16], rows 6,7 zero
#define SZ_IND    (8 * 16)
#define LW_F      (IND_F + SZ_IND)
#define LB_F      (LW_F + HID * INPUT)
#define BIAS_F    (LB_F + 8)                 // ull[2][4][64][4] = 4096 floats
#define SZ_BIAS   (2 * LAYERS * HID * 8)
#define SMEM_TOTAL_B (FB_B + (BIAS_F + SZ_BIAS) * 4)

__global__ void __launch_bounds__(NTHR, 1)
lstm36206574305735_main(const float* __restrict__ x,
                        const float* __restrict__ eB,
                        const float* __restrict__ dB,
                        const float* __restrict__ linW,
                        const float* __restrict__ linB,
                        float* __restrict__ out)
{
    extern __shared__ char sm[];
    const uint32_t ring_u = smem_u32(sm);
    const uint32_t mbar_u = ring_u + MBAR_B;
    float* fb   = (float*)(sm + FB_B);
    float* hd   = fb + HD_F;
    float* ind  = fb + IND_F;
    float* lw_s = fb + LW_F;
    float* lb_s = fb + LB_F;
    ull*   bias = (ull*)(fb + BIAS_F);

    const int tid = threadIdx.x;
    const int hh  = tid >> 2;
    const int bg  = tid & 3;
    const int b0  = blockIdx.x * NB;

    if (tid == 0) {
        for (int s = 0; s < NSLOT; s++)
            asm volatile("mbarrier.init.shared.b64 [%0], 1;"
                         :: "r"(mbar_u + s * 8) : "memory");
        asm volatile("fence.proxy.async.shared::cta;" ::: "memory");
    }
    for (int i = tid; i < SZ_HD; i += NTHR) hd[i] = 0.0f;
    for (int i = tid; i < SZ_IND; i += NTHR) ind[i] = 0.0f;
    for (int i = tid; i < HID * INPUT; i += NTHR) {
        int h2 = i / INPUT, ii2 = i % INPUT;
        lw_s[h2 * INPUT + ii2] = linW[ii2 * HID + h2];
    }
    if (tid < INPUT) lb_s[tid] = linB[tid];
    for (int u = tid; u < 2 * LAYERS * HID; u += NTHR) {
        int phase = u >> 8, l = (u >> 6) & 3, hx = u & 63;
        const float* B = phase ? dB : eB;
        bias[u * 4 + 0] = dup2(B[l * GATES + hx]);
        bias[u * 4 + 1] = dup2(B[l * GATES + HID + hx]);
        bias[u * 4 + 2] = dup2(B[l * GATES + 2 * HID + hx]);
        bias[u * 4 + 3] = dup2(B[l * GATES + 3 * HID + hx]);
    }
    __syncthreads();

    auto issue_one = [&](int G) {
        if (G >= TOTALC) return;
        int s = G % NSLOT;
        int cc = G % CPS;
        const float4* src = (G < 120 * CPS ? g_stream_e : g_stream_d)
                            + (size_t)cc * CHUNK_F4;
        uint32_t bytes = (cc == 2) ? (uint32_t)W0_BYTES : (uint32_t)CHUNK_BYTES;
        uint32_t mb = mbar_u + s * 8;
        asm volatile("mbarrier.arrive.expect_tx.shared.b64 _, [%0], %1;"
                     :: "r"(mb), "r"(bytes) : "memory");
        asm volatile("cp.async.bulk.shared::cluster.global.mbarrier::complete_tx::bytes "
                     "[%0], [%1], %2, [%3];"
                     :: "r"(ring_u + (uint32_t)s * CHUNK_BYTES), "l"(src),
                        "r"(bytes), "r"(mb) : "memory");
    };
    if (tid == 0)
        for (int g = 0; g < NSLOT; g++) issue_one(g);

    int Gi = NSLOT, cap = NSLOT, Cg = 0;
    unsigned par = 0;

    auto next_chunk = [&]() -> const float4* {
        int s = Cg % NSLOT;
        wait_parity(mbar_u + s * 8, (par >> s) & 1u);
        par ^= (1u << s);
        Cg++;
        return (const float4*)(sm + (size_t)s * CHUNK_BYTES);
    };
    auto barrier_issue = [&](int add) {
        __syncthreads();
        cap += add;
        if (tid == 0)
            for (; Gi < cap; Gi++) issue_one(Gi);
        else
            Gi = cap;
    };

    float c_reg[LAYERS][4];
#pragma unroll
    for (int l = 0; l < LAYERS; l++)
#pragma unroll
        for (int bi = 0; bi < 4; bi++) c_reg[l][bi] = 0.0f;

    const int  bb  = tid / INPUT;
    const int  ii  = tid % INPUT;
    const bool isx = tid < INPUT * NB;
    float xreg = 0.0f;
    if (isx) xreg = x[(size_t)(b0 + bb) * INPUT + ii];

    // layer: Whh gemv(old h[l]) -> BAR(+issue) -> Wih/W0 gemv(new h[l-1]/ind) -> cell
    auto do_layer = [&](int phase, int l, int add, bool isL0) {
        const ull* bv = bias + ((phase * LAYERS + l) * HID + hh) * 4;
        ull acc[8];
        acc[0] = acc[1] = bv[0];
        acc[2] = acc[3] = bv[1];
        acc[4] = acc[5] = bv[2];
        acc[6] = acc[7] = bv[3];

        const float* hl = hd + l * (HID * 16);
        { const float4* wp = next_chunk(); gemv_s<32>(wp, hl,       hh, bg, acc); }
        { const float4* wp = next_chunk(); gemv_s<32>(wp, hl + 512, hh, bg, acc); }

        barrier_issue(add);

        if (isL0) {
            const float4* wp = next_chunk(); gemv_s<8>(wp, ind, hh, bg, acc);
        } else {
            const float* hp = hd + (l - 1) * (HID * 16);
            { const float4* wp = next_chunk(); gemv_s<32>(wp, hp,       hh, bg, acc); }
            { const float4* wp = next_chunk(); gemv_s<32>(wp, hp + 512, hh, bg, acc); }
        }

        float2 ai0 = unpk(acc[0]), ai1 = unpk(acc[1]);
        float2 af0 = unpk(acc[2]), af1 = unpk(acc[3]);
        float2 ag0 = unpk(acc[4]), ag1 = unpk(acc[5]);
        float2 ao0 = unpk(acc[6]), ao1 = unpk(acc[7]);
        float ai[4] = {ai0.x, ai0.y, ai1.x, ai1.y};
        float af[4] = {af0.x, af0.y, af1.x, af1.y};
        float ag[4] = {ag0.x, ag0.y, ag1.x, ag1.y};
        float ao[4] = {ao0.x, ao0.y, ao1.x, ao1.y};
        float hout[4];
#pragma unroll
        for (int bi = 0; bi < 4; bi++) {
            float c = fmaf(fsig(af[bi]), c_reg[l][bi], fsig(ai[bi]) * ftanh_(ag[bi]));
            c_reg[l][bi] = c;
            hout[bi] = fsig(ao[bi]) * ftanh_(c);
        }
        float* hrow = hd + (l * HID + hh) * 16 + bg * 4;
        *(float4*)hrow = make_float4(hout[0], hout[1], hout[2], hout[3]);
    };

    // -------- encoder --------
    for (int t = 0; t < SEQ_LEN; t++) {
        if (isx) {
            ind[ii * 16 + bb] = xreg;
            if (t + 1 < SEQ_LEN)
                xreg = x[((size_t)(t + 1) * BATCH + b0 + bb) * INPUT + ii];
        }
        do_layer(0, 0, t == 0 ? 2 : 4, true);
        do_layer(0, 1, 3, false);
        do_layer(0, 2, 4, false);
        do_layer(0, 3, 4, false);
    }
    // ind still holds x[SEQ_LEN-1] — decoder seed

    // -------- decoder --------
    for (int t = 0; t < TLEN; t++) {
        do_layer(1, 0, 4, true);
        do_layer(1, 1, 3, false);
        do_layer(1, 2, 4, false);
        do_layer(1, 3, 4, false);

        __syncthreads();   // h[3] visible to all warps
        if (isx) {
            const float* htop = hd + 3 * (HID * 16);
            float v = lb_s[ii];
#pragma unroll 8
            for (int h2 = 0; h2 < HID; h2++)
                v += lw_s[h2 * INPUT + ii] * htop[h2 * 16 + bb];
            out[((size_t)t * BATCH + b0 + bb) * INPUT + ii] = v;
            ind[ii * 16 + bb] = v;
        }
    }
}

extern "C" void kernel_launch(void* const* d_in, const int* in_sizes, int n_in,
                              void* d_out, int out_size)
{
    const float* x    = (const float*)d_in[0];
    const float* eW0  = (const float*)d_in[1];
    const float* eWih = (const float*)d_in[2];
    const float* eWhh = (const float*)d_in[3];
    const float* eB   = (const float*)d_in[4];
    const float* dW0  = (const float*)d_in[5];
    const float* dWih = (const float*)d_in[6];
    const float* dWhh = (const float*)d_in[7];
    const float* dB   = (const float*)d_in[8];
    const float* linW = (const float*)d_in[9];
    const float* linB = (const float*)d_in[10];
    float* out = (float*)d_out;

    lstm36206574305735_pack<<<240, 256>>>(eW0, eWih, eWhh, dW0, dWih, dWhh);

    cudaFuncSetAttribute(lstm36206574305735_main,
                         cudaFuncAttributeMaxDynamicSharedMemorySize, SMEM_TOTAL_B);
    lstm36206574305735_main<<<NCTA, NTHR, SMEM_TOTAL_B>>>(x, eB, dB, linW, linB, out);
}

// round 8
// speedup vs baseline: 1.4920x; 1.0029x over previous
#include <cuda_runtime.h>
#include <cstdint>

#define SEQ_LEN  120
#define BATCH    2048
#define INPUT    6
#define HID      64
#define GATES    256
#define LAYERS   4
#define TLEN     120
#define NB       16
#define NCTA     (BATCH / NB)   // 128
#define NTHR     512            // 2 kg x 64 hh x 4 bg

#define CHUNK_ROWS 32
#define CHUNK_F4   (CHUNK_ROWS * HID)     // 2048 float4
#define CHUNK_BYTES (CHUNK_F4 * 16)       // 32768
#define W0_BYTES   (8 * HID * 16)         // 8192
#define NSLOT      5
#define CPS        15
#define TOTALC     (240 * CPS)

typedef unsigned long long ull;

// chunk order per step: c0,c1 = Whh L0 halves; c2 = W0 (8 k-rows);
// per l>=1, base 3+4(l-1): Whh l (2 chunks), then Wih l (2 chunks)
__device__ float4 g_stream_e[CPS * CHUNK_F4];
__device__ float4 g_stream_d[CPS * CHUNK_F4];

__global__ void lstm36206574305735_pack(
    const float* __restrict__ eW0, const float* __restrict__ eWih,
    const float* __restrict__ eWhh, const float* __restrict__ dW0,
    const float* __restrict__ dWih, const float* __restrict__ dWhh)
{
    const int tot = 2 * CPS * CHUNK_F4;
    for (int idx = blockIdx.x * blockDim.x + threadIdx.x; idx < tot;
         idx += gridDim.x * blockDim.x) {
        int p  = idx / (CPS * CHUNK_F4);
        int r  = idx % (CPS * CHUNK_F4);
        int c  = r / CHUNK_F4;
        int rr = r % CHUNK_F4;
        int kc = rr / HID;
        int hh = rr % HID;
        const float* W0  = p ? dW0  : eW0;
        const float* Wih = p ? dWih : eWih;
        const float* Whh = p ? dWhh : eWhh;
        float4 v = make_float4(0.f, 0.f, 0.f, 0.f);
        if (c == 2) {
            if (kc < INPUT) {
                v.x = W0[(0 * HID + hh) * INPUT + kc];
                v.y = W0[(1 * HID + hh) * INPUT + kc];
                v.z = W0[(2 * HID + hh) * INPUT + kc];
                v.w = W0[(3 * HID + hh) * INPUT + kc];
            }
        } else {
            const float* W; int k;
            if (c < 2) { W = Whh; k = c * CHUNK_ROWS + kc; }            // Whh L0
            else {
                int l  = (c - 3) / 4 + 1;
                int cc = (c - 3) % 4;
                if (cc < 2) { W = Whh + (size_t)l * GATES * HID;        k = cc * CHUNK_ROWS + kc; }
                else        { W = Wih + (size_t)(l - 1) * GATES * HID;  k = (cc - 2) * CHUNK_ROWS + kc; }
            }
            v.x = W[(0 * HID + hh) * HID + k];
            v.y = W[(1 * HID + hh) * HID + k];
            v.z = W[(2 * HID + hh) * HID + k];
            v.w = W[(3 * HID + hh) * HID + k];
        }
        (p ? g_stream_d : g_stream_e)[r] = v;
    }
}

// ---- helpers ----------------------------------------------------------------
__device__ __forceinline__ void ffma2(ull& d, ull a, ull b) {
    asm("fma.rn.f32x2 %0, %1, %2, %0;" : "+l"(d) : "l"(a), "l"(b));
}
__device__ __forceinline__ ull dup2(float a) {
    ull v; asm("mov.b64 %0, {%1, %1};" : "=l"(v) : "f"(a)); return v;
}
__device__ __forceinline__ float2 unpk(ull v) {
    float2 r; asm("mov.b64 {%0, %1}, %2;" : "=f"(r.x), "=f"(r.y) : "l"(v)); return r;
}
__device__ __forceinline__ float fsig(float x) {
    return __fdividef(1.0f, 1.0f + __expf(-x));
}
__device__ __forceinline__ float ftanh_(float x) {
    return 2.0f * fsig(2.0f * x) - 1.0f;
}
__device__ __forceinline__ uint32_t smem_u32(const void* p) {
    uint32_t a;
    asm("{ .reg .u64 t; cvta.to.shared.u64 t, %1; cvt.u32.u64 %0, t; }"
        : "=r"(a) : "l"(p));
    return a;
}
__device__ __forceinline__ void wait_parity(uint32_t mb, uint32_t parity) {
    asm volatile(
        "{\n\t"
        ".reg .pred P;\n\t"
        "WLOOP_%=:\n\t"
        "mbarrier.try_wait.parity.acquire.cta.shared::cta.b64 P, [%0], %1, 0x989680;\n\t"
        "@P bra WDONE_%=;\n\t"
        "bra WLOOP_%=;\n\t"
        "WDONE_%=:\n\t"
        "}"
        :: "r"(mb), "r"(parity) : "memory");
}

// per k = 2 LDS.128 + 4 dup MOVs + 8 FFMA2 (proven R5 mix)
template <int K>
__device__ __forceinline__ void gemv_s(const float4* __restrict__ wslot,
                                       const float* __restrict__ hs,
                                       int hh, int bg, ull acc[8])
{
#pragma unroll 8
    for (int k = 0; k < K; k++) {
        float4 w4 = wslot[k * HID + hh];
        ulonglong2 hv = *(const ulonglong2*)(hs + k * 16 + bg * 4);
        ull wi = dup2(w4.x), wf = dup2(w4.y), wg = dup2(w4.z), wo = dup2(w4.w);
        ffma2(acc[0], wi, hv.x); ffma2(acc[1], wi, hv.y);
        ffma2(acc[2], wf, hv.x); ffma2(acc[3], wf, hv.y);
        ffma2(acc[4], wg, hv.x); ffma2(acc[5], wg, hv.y);
        ffma2(acc[6], wo, hv.x); ffma2(acc[7], wo, hv.y);
    }
}

// ---- smem layout ------------------------------------------------------------
#define RING_SZ   (NSLOT * CHUNK_BYTES)     // 163840
#define MBAR_B    RING_SZ
#define FB_B      (RING_SZ + 64)
#define HD_F      0                          // [4][64][16] single-buffered h
#define SZ_HD     (LAYERS * HID * 16)        // 4096
#define IND_F     (HD_F + SZ_HD)             // [8][16], rows 6,7 zero
#define SZ_IND    (8 * 16)
#define LW_F      (IND_F + SZ_IND)
#define LB_F      (LW_F + HID * INPUT)
#define BIAS_F    (LB_F + 8)                 // ull[2][4][64][4] = 4096 floats
#define SZ_BIAS   (2 * LAYERS * HID * 8)
#define PART_F    (BIAS_F + SZ_BIAS)         // ull[256][10] = 5120 floats (16B-aligned rows)
#define SZ_PART   (256 * 10 * 2)
#define SMEM_TOTAL_B (FB_B + (PART_F + SZ_PART) * 4)   // ~219KB

__global__ void __launch_bounds__(NTHR, 1)
lstm36206574305735_main(const float* __restrict__ x,
                        const float* __restrict__ eB,
                        const float* __restrict__ dB,
                        const float* __restrict__ linW,
                        const float* __restrict__ linB,
                        float* __restrict__ out)
{
    extern __shared__ char sm[];
    const uint32_t ring_u = smem_u32(sm);
    const uint32_t mbar_u = ring_u + MBAR_B;
    float* fb   = (float*)(sm + FB_B);
    float* hd   = fb + HD_F;
    float* ind  = fb + IND_F;
    float* lw_s = fb + LW_F;
    float* lb_s = fb + LB_F;
    ull*   bias = (ull*)(fb + BIAS_F);
    ull*   part = (ull*)(fb + PART_F);

    const int tid = threadIdx.x;
    const int kg  = tid >> 8;      // 0: k 0..31 + bias + epilogue; 1: k 32..63
    const int r   = tid & 255;
    const int hh  = r >> 2;
    const int bg  = r & 3;
    const int b0  = blockIdx.x * NB;

    if (tid == 0) {
        for (int s = 0; s < NSLOT; s++)
            asm volatile("mbarrier.init.shared.b64 [%0], 1;"
                         :: "r"(mbar_u + s * 8) : "memory");
        asm volatile("fence.proxy.async.shared::cta;" ::: "memory");
    }
    for (int i = tid; i < SZ_HD; i += NTHR) hd[i] = 0.0f;
    for (int i = tid; i < SZ_IND; i += NTHR) ind[i] = 0.0f;
    for (int i = tid; i < HID * INPUT; i += NTHR) {
        int h2 = i / INPUT, ii2 = i % INPUT;
        lw_s[h2 * INPUT + ii2] = linW[ii2 * HID + h2];
    }
    if (tid < INPUT) lb_s[tid] = linB[tid];
    for (int u = tid; u < 2 * LAYERS * HID; u += NTHR) {
        int phase = u >> 8, l = (u >> 6) & 3, hx = u & 63;
        const float* B = phase ? dB : eB;
        bias[u * 4 + 0] = dup2(B[l * GATES + hx]);
        bias[u * 4 + 1] = dup2(B[l * GATES + HID + hx]);
        bias[u * 4 + 2] = dup2(B[l * GATES + 2 * HID + hx]);
        bias[u * 4 + 3] = dup2(B[l * GATES + 3 * HID + hx]);
    }
    __syncthreads();

    auto issue_one = [&](int G) {
        if (G >= TOTALC) return;
        int s = G % NSLOT;
        int cc = G % CPS;
        const float4* src = (G < 120 * CPS ? g_stream_e : g_stream_d)
                            + (size_t)cc * CHUNK_F4;
        uint32_t bytes = (cc == 2) ? (uint32_t)W0_BYTES : (uint32_t)CHUNK_BYTES;
        uint32_t mb = mbar_u + s * 8;
        asm volatile("mbarrier.arrive.expect_tx.shared.b64 _, [%0], %1;"
                     :: "r"(mb), "r"(bytes) : "memory");
        asm volatile("cp.async.bulk.shared::cluster.global.mbarrier::complete_tx::bytes "
                     "[%0], [%1], %2, [%3];"
                     :: "r"(ring_u + (uint32_t)s * CHUNK_BYTES), "l"(src),
                        "r"(bytes), "r"(mb) : "memory");
    };
    if (tid == 0)
        for (int g = 0; g < NSLOT; g++) issue_one(g);

    int Gi = NSLOT, cap = NSLOT;

    auto wait_chunk = [&](int G) -> const float4* {
        int s = G % NSLOT;
        wait_parity(mbar_u + s * 8, (unsigned)((G / NSLOT) & 1));
        return (const float4*)(sm + (size_t)s * CHUNK_BYTES);
    };
    auto barrier_issue = [&](int add) {
        __syncthreads();
        cap += add;
        if (tid == 0)
            for (; Gi < cap; Gi++) issue_one(Gi);
        else
            Gi = cap;
    };

    float c_reg[LAYERS][4];
#pragma unroll
    for (int l = 0; l < LAYERS; l++)
#pragma unroll
        for (int bi = 0; bi < 4; bi++) c_reg[l][bi] = 0.0f;

    const int  bb  = tid / INPUT;
    const int  ii  = tid % INPUT;
    const bool isx = tid < INPUT * NB;     // subset of kg0
    float xreg = 0.0f;
    if (isx) xreg = x[(size_t)(b0 + bb) * INPUT + ii];

    const float ONEf = 1.0f;
    const ull ONE = dup2(ONEf);

    // layer: A = Whh gemv(old h[l], split by kg) -> BAR(+2)
    //        B = Wih/W0 gemv(new h[l-1]/ind, split) ; kg1 stores partials
    //        -> BAR(+2/+1) ; kg0 reduces + cell epilogue -> h[l]
    auto do_layer = [&](int phase, int l, int cbase, bool isL0) {
        ull acc[8];
        if (kg == 0) {
            const ull* bv = bias + ((phase * LAYERS + l) * HID + hh) * 4;
            acc[0] = acc[1] = bv[0];
            acc[2] = acc[3] = bv[1];
            acc[4] = acc[5] = bv[2];
            acc[6] = acc[7] = bv[3];
        } else {
#pragma unroll
            for (int i = 0; i < 8; i++) acc[i] = 0ull;
        }

        const float* hl = hd + l * (HID * 16);
        {
            const float4* wp = wait_chunk(cbase + kg);
            gemv_s<32>(wp, hl + kg * 512, hh, bg, acc);
        }
        barrier_issue(2);

        if (isL0) {
            if (kg == 0) {
                const float4* wp = wait_chunk(cbase + 2);
                gemv_s<8>(wp, ind, hh, bg, acc);
            }
        } else {
            const float* hp = hd + (l - 1) * (HID * 16);
            const float4* wp = wait_chunk(cbase + 2 + kg);
            gemv_s<32>(wp, hp + kg * 512, hh, bg, acc);
        }

        if (kg == 1) {
            ulonglong2* pr = (ulonglong2*)(part + r * 10);
            pr[0] = make_ulonglong2(acc[0], acc[1]);
            pr[1] = make_ulonglong2(acc[2], acc[3]);
            pr[2] = make_ulonglong2(acc[4], acc[5]);
            pr[3] = make_ulonglong2(acc[6], acc[7]);
        }
        barrier_issue(isL0 ? 1 : 2);

        if (kg == 0) {
            const ulonglong2* pr = (const ulonglong2*)(part + r * 10);
            ulonglong2 p0 = pr[0], p1 = pr[1], p2 = pr[2], p3 = pr[3];
            ffma2(acc[0], p0.x, ONE); ffma2(acc[1], p0.y, ONE);
            ffma2(acc[2], p1.x, ONE); ffma2(acc[3], p1.y, ONE);
            ffma2(acc[4], p2.x, ONE); ffma2(acc[5], p2.y, ONE);
            ffma2(acc[6], p3.x, ONE); ffma2(acc[7], p3.y, ONE);

            float2 ai0 = unpk(acc[0]), ai1 = unpk(acc[1]);
            float2 af0 = unpk(acc[2]), af1 = unpk(acc[3]);
            float2 ag0 = unpk(acc[4]), ag1 = unpk(acc[5]);
            float2 ao0 = unpk(acc[6]), ao1 = unpk(acc[7]);
            float ai[4] = {ai0.x, ai0.y, ai1.x, ai1.y};
            float af[4] = {af0.x, af0.y, af1.x, af1.y};
            float ag[4] = {ag0.x, ag0.y, ag1.x, ag1.y};
            float ao[4] = {ao0.x, ao0.y, ao1.x, ao1.y};
            float hout[4];
#pragma unroll
            for (int bi = 0; bi < 4; bi++) {
                float c = fmaf(fsig(af[bi]), c_reg[l][bi],
                               fsig(ai[bi]) * ftanh_(ag[bi]));
                c_reg[l][bi] = c;
                hout[bi] = fsig(ao[bi]) * ftanh_(c);
            }
            float* hrow = hd + (l * HID + hh) * 16 + bg * 4;
            *(float4*)hrow = make_float4(hout[0], hout[1], hout[2], hout[3]);
        }
    };

    // -------- encoder --------
    int Gstep = 0;
    for (int t = 0; t < SEQ_LEN; t++) {
        if (isx) {
            ind[ii * 16 + bb] = xreg;
            if (t + 1 < SEQ_LEN)
                xreg = x[((size_t)(t + 1) * BATCH + b0 + bb) * INPUT + ii];
        }
        do_layer(0, 0, Gstep + 0,  true);
        do_layer(0, 1, Gstep + 3,  false);
        do_layer(0, 2, Gstep + 7,  false);
        do_layer(0, 3, Gstep + 11, false);
        Gstep += CPS;
    }
    // ind still holds x[SEQ_LEN-1] — decoder seed

    // -------- decoder --------
    for (int t = 0; t < TLEN; t++) {
        do_layer(1, 0, Gstep + 0,  true);
        do_layer(1, 1, Gstep + 3,  false);
        do_layer(1, 2, Gstep + 7,  false);
        do_layer(1, 3, Gstep + 11, false);
        Gstep += CPS;

        __syncthreads();   // h[3] from kg0 epilogue visible to all
        if (isx) {
            const float* htop = hd + 3 * (HID * 16);
            float v = lb_s[ii];
#pragma unroll 8
            for (int h2 = 0; h2 < HID; h2++)
                v += lw_s[h2 * INPUT + ii] * htop[h2 * 16 + bb];
            out[((size_t)t * BATCH + b0 + bb) * INPUT + ii] = v;
            ind[ii * 16 + bb] = v;
        }
    }
}

extern "C" void kernel_launch(void* const* d_in, const int* in_sizes, int n_in,
                              void* d_out, int out_size)
{
    const float* x    = (const float*)d_in[0];
    const float* eW0  = (const float*)d_in[1];
    const float* eWih = (const float*)d_in[2];
    const float* eWhh = (const float*)d_in[3];
    const float* eB   = (const float*)d_in[4];
    const float* dW0  = (const float*)d_in[5];
    const float* dWih = (const float*)d_in[6];
    const float* dWhh = (const float*)d_in[7];
    const float* dB   = (const float*)d_in[8];
    const float* linW = (const float*)d_in[9];
    const float* linB = (const float*)d_in[10];
    float* out = (float*)d_out;

    lstm36206574305735_pack<<<240, 256>>>(eW0, eWih, eWhh, dW0, dWih, dWhh);

    cudaFuncSetAttribute(lstm36206574305735_main,
                         cudaFuncAttributeMaxDynamicSharedMemorySize, SMEM_TOTAL_B);
    lstm36206574305735_main<<<NCTA, NTHR, SMEM_TOTAL_B>>>(x, eB, dB, linW, linB, out);
}